// round 6
// baseline (speedup 1.0000x reference)
#include <cuda_runtime.h>
#include <cuda_fp16.h>
#include <cmath>
#include <cstdint>

#define T_ 4
#define B_ 8
#define C_ 512
#define N_ 1024
#define TB 32
#define CN (C_*N_)          // 524288
#define TBCN (TB*CN)        // 16777216
#define PER_T (B_*CN)

// Scratch (static device globals — no runtime allocation)
__device__ __half gh_q[TBCN];        // q spikes [t][b][c][n] fp16 (binary, exact)
__device__ __half gh_k[TBCN];
__device__ __half gh_v[TBCN];
__device__ __half gh_a[TBCN];        // attn spikes
__device__ float  g_kv[TB*8*64*64];  // integer counts <=1024, exact fp32

#define WSCALE     2048.0f
#define WSCALE_INV 4.8828125e-4f     // 2^-11, exact

// ============================================================================
// helpers
// ============================================================================
__device__ __forceinline__ uint32_t smem_u32(const void* p) {
    uint32_t a;
    asm("{ .reg .u64 t; cvta.to.shared.u64 t, %1; cvt.u32.u64 %0, t; }" : "=r"(a) : "l"(p));
    return a;
}
__device__ __forceinline__ uint32_t packh(__half a, __half b) {
    __half2 h = __halves2half2(a, b);
    return *(uint32_t*)&h;
}
__device__ __forceinline__ void ldmx4(uint32_t* r, uint32_t addr) {
    asm volatile("ldmatrix.sync.aligned.m8n8.x4.shared.b16 {%0,%1,%2,%3}, [%4];"
                 : "=r"(r[0]), "=r"(r[1]), "=r"(r[2]), "=r"(r[3]) : "r"(addr));
}
__device__ __forceinline__ void ldmx4t(uint32_t* r, uint32_t addr) {
    asm volatile("ldmatrix.sync.aligned.m8n8.x4.trans.shared.b16 {%0,%1,%2,%3}, [%4];"
                 : "=r"(r[0]), "=r"(r[1]), "=r"(r[2]), "=r"(r[3]) : "r"(addr));
}
__device__ __forceinline__ void mma16(float* c, const uint32_t* a, const uint32_t* b) {
    asm volatile("mma.sync.aligned.m16n8k16.row.col.f32.f16.f16.f32 "
                 "{%0,%1,%2,%3}, {%4,%5,%6,%7}, {%8,%9}, {%0,%1,%2,%3};"
                 : "+f"(c[0]), "+f"(c[1]), "+f"(c[2]), "+f"(c[3])
                 : "r"(a[0]), "r"(a[1]), "r"(a[2]), "r"(a[3]), "r"(b[0]), "r"(b[1]));
}
// exact reference LIF step: v' = v + (x - v)*0.5 ; spike >= thr ; hard reset
__device__ __forceinline__ float lif_step(float& vv, float x, float thr) {
    vv = __fadd_rn(vv, __fmul_rn(__fsub_rn(x, vv), 0.5f));
    float s = (vv >= thr) ? 1.0f : 0.0f;
    if (vv >= thr) vv = 0.0f;
    return s;
}

// ============================================================================
// Fused fp16-split GEMM + BN + multi-step LIF.
// For b fixed, loops t=0..3; LIF membrane state in SMEM (per-thread-owned).
// NSPLIT=3: fp32 input X [z][c][n], 3xFP16 split (~2^-22 rel).
// NSPLIT=2: fp16 binary spike input (exact), Whi*B + Wlo*B.
// OUT: __half (spikes) or float (final output spikes).
// CTA 128x128, 8 warps of 64x32, K-chunk 16, double-buffered.
// ============================================================================
template<int NSPLIT, typename TOUT>
__global__ __launch_bounds__(256, 2) void gemm_lif(
    const float* __restrict__ W, const void* __restrict__ Xv,
    TOUT* __restrict__ OUT,
    const float* __restrict__ gamma, const float* __restrict__ beta,
    const float* __restrict__ bias, float inv, float thr)
{
    extern __shared__ char smbuf[];
    // panels: Ah [2][4096] @0, Al @8192, Bh @16384, Bl @24576; V @32768 [128][130] f32
    const uint32_t sbase = smem_u32(smbuf);
    float* Vst = (float*)(smbuf + 32768);

    const int tid  = threadIdx.x;
    const int lane = tid & 31;
    const int wid  = tid >> 5;
    const int wm   = (wid >> 2) * 64;
    const int wn   = (wid & 3) * 32;
    const int b  = blockIdx.z;
    const int m0 = blockIdx.y * 128;
    const int n0 = blockIdx.x * 128;

    // init membrane state
#pragma unroll
    for (int i = tid; i < 128 * 130 / 2; i += 256)
        *(float2*)&Vst[i * 2] = make_float2(0.0f, 0.0f);

    // loader indices
    const int mA = tid & 127;
    const int jA = (tid >> 7) * 8;
    const int kB = tid >> 5;
    const int nB = (tid & 31) * 4;
    const float* Wrow = W + (size_t)(m0 + mA) * C_ + jA;
    const uint32_t abyte = (uint32_t)((mA * 2 + ((jA >> 3) ^ ((mA >> 2) & 1))) * 16);
    const uint32_t bbyte0 = (uint32_t)(kB * 256 + (((nB >> 3) ^ (kB & 7))) * 16 + (nB & 7) * 2);
    const int kB2 = kB + 8;
    const uint32_t bbyte1 = (uint32_t)(kB2 * 256 + (((nB >> 3) ^ (kB2 & 7))) * 16 + (nB & 7) * 2);

    // ldmatrix lane offsets
    const int mrel = (lane & 7) | (((lane >> 3) & 1) << 3);
    const int hA   = (lane >> 4) & 1;
    uint32_t offA[4];
#pragma unroll
    for (int mt = 0; mt < 4; mt++) {
        int m = wm + mt * 16 + mrel;
        offA[mt] = (uint32_t)((m * 2 + (hA ^ ((m >> 2) & 1))) * 16);
    }
    const int krel = (lane & 7) | (((lane >> 3) & 1) << 3);
    const int nrel = ((lane >> 4) & 1) * 8;
    uint32_t offB[2];
#pragma unroll
    for (int p = 0; p < 2; p++) {
        int n = wn + p * 16 + nrel;
        offB[p] = (uint32_t)(krel * 256 + (((n >> 3) ^ (krel & 7))) * 16);
    }

    __syncthreads();   // V init visible (each thread reads only its own cells anyway)

#pragma unroll 1
    for (int t = 0; t < 4; t++) {
        const size_t zoff = (size_t)(t * 8 + b) * CN;
        const float*  Xf = (const float*)Xv + zoff;
        const __half* Xh = (const __half*)Xv + zoff;

        float acc[4][4][4];
#pragma unroll
        for (int i = 0; i < 4; i++)
#pragma unroll
            for (int j = 0; j < 4; j++)
#pragma unroll
                for (int e = 0; e < 4; e++) acc[i][j][e] = 0.0f;

        float4 wa0, wa1, xb0, xb1;
        uint2 ub0, ub1;

        auto LDG = [&](int ch) {
            const int kb = ch * 16;
            wa0 = *(const float4*)(Wrow + kb);
            wa1 = *(const float4*)(Wrow + kb + 4);
            if (NSPLIT >= 3) {
                xb0 = *(const float4*)(Xf + (size_t)(kb + kB) * N_ + n0 + nB);
                xb1 = *(const float4*)(Xf + (size_t)(kb + 8 + kB) * N_ + n0 + nB);
            } else {
                ub0 = *(const uint2*)(Xh + (size_t)(kb + kB) * N_ + n0 + nB);
                ub1 = *(const uint2*)(Xh + (size_t)(kb + 8 + kB) * N_ + n0 + nB);
            }
        };

        auto STS = [&](int st) {
            char* Ah = smbuf + st * 4096;
            char* Al = smbuf + 8192 + st * 4096;
            char* Bh = smbuf + 16384 + st * 4096;
            char* Bl = smbuf + 24576 + st * 4096;
            float wv[8] = {wa0.x, wa0.y, wa0.z, wa0.w, wa1.x, wa1.y, wa1.z, wa1.w};
            uint32_t ph[4], pl[4];
#pragma unroll
            for (int e = 0; e < 4; e++) {
                float s0 = wv[2 * e] * WSCALE, s1 = wv[2 * e + 1] * WSCALE;
                __half h0 = __float2half_rn(s0), h1 = __float2half_rn(s1);
                __half l0 = __float2half_rn(s0 - __half2float(h0));
                __half l1 = __float2half_rn(s1 - __half2float(h1));
                ph[e] = packh(h0, h1);
                pl[e] = packh(l0, l1);
            }
            *(uint4*)(Ah + abyte) = make_uint4(ph[0], ph[1], ph[2], ph[3]);
            *(uint4*)(Al + abyte) = make_uint4(pl[0], pl[1], pl[2], pl[3]);
            if (NSPLIT >= 3) {
                __half h0 = __float2half_rn(xb0.x), h1 = __float2half_rn(xb0.y);
                __half h2 = __float2half_rn(xb0.z), h3 = __float2half_rn(xb0.w);
                __half l0 = __float2half_rn(xb0.x - __half2float(h0));
                __half l1 = __float2half_rn(xb0.y - __half2float(h1));
                __half l2 = __float2half_rn(xb0.z - __half2float(h2));
                __half l3 = __float2half_rn(xb0.w - __half2float(h3));
                *(uint2*)(Bh + bbyte0) = make_uint2(packh(h0, h1), packh(h2, h3));
                *(uint2*)(Bl + bbyte0) = make_uint2(packh(l0, l1), packh(l2, l3));
                h0 = __float2half_rn(xb1.x); h1 = __float2half_rn(xb1.y);
                h2 = __float2half_rn(xb1.z); h3 = __float2half_rn(xb1.w);
                l0 = __float2half_rn(xb1.x - __half2float(h0));
                l1 = __float2half_rn(xb1.y - __half2float(h1));
                l2 = __float2half_rn(xb1.z - __half2float(h2));
                l3 = __float2half_rn(xb1.w - __half2float(h3));
                *(uint2*)(Bh + bbyte1) = make_uint2(packh(h0, h1), packh(h2, h3));
                *(uint2*)(Bl + bbyte1) = make_uint2(packh(l0, l1), packh(l2, l3));
            } else {
                *(uint2*)(Bh + bbyte0) = ub0;   // binary spikes: exact fp16 already
                *(uint2*)(Bh + bbyte1) = ub1;
            }
        };

        auto COMP = [&](int st) {
            const uint32_t aHi = sbase + st * 4096;
            const uint32_t aLo = sbase + 8192 + st * 4096;
            const uint32_t bHi = sbase + 16384 + st * 4096;
            const uint32_t bLo = sbase + 24576 + st * 4096;

            uint32_t ah[4][4], bh[4][2];
#pragma unroll
            for (int mt = 0; mt < 4; mt++) ldmx4(ah[mt], aHi + offA[mt]);
#pragma unroll
            for (int p = 0; p < 2; p++) {
                uint32_t tr[4];
                ldmx4t(tr, bHi + offB[p]);
                bh[2 * p][0] = tr[0]; bh[2 * p][1] = tr[1];
                bh[2 * p + 1][0] = tr[2]; bh[2 * p + 1][1] = tr[3];
            }
#pragma unroll
            for (int mt = 0; mt < 4; mt++)
#pragma unroll
                for (int nt = 0; nt < 4; nt++) mma16(acc[mt][nt], ah[mt], bh[nt]);
            if (NSPLIT >= 3) {
                uint32_t bl[4][2];
#pragma unroll
                for (int p = 0; p < 2; p++) {
                    uint32_t tr[4];
                    ldmx4t(tr, bLo + offB[p]);
                    bl[2 * p][0] = tr[0]; bl[2 * p][1] = tr[1];
                    bl[2 * p + 1][0] = tr[2]; bl[2 * p + 1][1] = tr[3];
                }
#pragma unroll
                for (int mt = 0; mt < 4; mt++)
#pragma unroll
                    for (int nt = 0; nt < 4; nt++) mma16(acc[mt][nt], ah[mt], bl[nt]);
            }
#pragma unroll
            for (int mt = 0; mt < 4; mt++) ldmx4(ah[mt], aLo + offA[mt]);
#pragma unroll
            for (int mt = 0; mt < 4; mt++)
#pragma unroll
                for (int nt = 0; nt < 4; nt++) mma16(acc[mt][nt], ah[mt], bh[nt]);
        };

        LDG(0);
        STS(0);
        __syncthreads();
#pragma unroll 1
        for (int ch = 0; ch < 32; ch++) {
            if (ch < 31) LDG(ch + 1);
            COMP(ch & 1);
            if (ch < 31) STS((ch + 1) & 1);
            __syncthreads();
        }

        // Epilogue: descale, BN (exact jax op order), LIF with v-state in SMEM.
        {
            const int rb = m0 + wm + (lane >> 2);
            const int cb = n0 + wn + 2 * (lane & 3);
            const int rlb = wm + (lane >> 2);          // local row in V
            const int clb = wn + 2 * (lane & 3);       // local col in V
            TOUT* Oz = OUT + zoff;
#pragma unroll
            for (int mt = 0; mt < 4; mt++) {
                int r0 = rb + mt * 16, r1 = r0 + 8;
                float g0 = gamma[r0], g1 = gamma[r1];
                float e0 = beta[r0],  e1 = beta[r1];
                float b0 = bias ? bias[r0] : 0.0f;
                float b1 = bias ? bias[r1] : 0.0f;
                float* vrow0 = &Vst[(rlb + mt * 16) * 130 + clb];
                float* vrow1 = vrow0 + 8 * 130;
#pragma unroll
                for (int nt = 0; nt < 4; nt++) {
                    int cc = cb + nt * 8;
                    float* c = acc[mt][nt];
                    float y0 = __fmul_rn(c[0], WSCALE_INV);
                    float y1 = __fmul_rn(c[1], WSCALE_INV);
                    float y2 = __fmul_rn(c[2], WSCALE_INV);
                    float y3 = __fmul_rn(c[3], WSCALE_INV);
                    if (bias) { y0 = __fadd_rn(y0, b0); y1 = __fadd_rn(y1, b0);
                                y2 = __fadd_rn(y2, b1); y3 = __fadd_rn(y3, b1); }
                    y0 = __fadd_rn(__fmul_rn(__fmul_rn(g0, y0), inv), e0);
                    y1 = __fadd_rn(__fmul_rn(__fmul_rn(g0, y1), inv), e0);
                    y2 = __fadd_rn(__fmul_rn(__fmul_rn(g1, y2), inv), e1);
                    y3 = __fadd_rn(__fmul_rn(__fmul_rn(g1, y3), inv), e1);
                    float vv0 = vrow0[nt * 8],     vv1 = vrow0[nt * 8 + 1];
                    float vv2 = vrow1[nt * 8],     vv3 = vrow1[nt * 8 + 1];
                    float s0 = lif_step(vv0, y0, thr);
                    float s1 = lif_step(vv1, y1, thr);
                    float s2 = lif_step(vv2, y2, thr);
                    float s3 = lif_step(vv3, y3, thr);
                    vrow0[nt * 8] = vv0; vrow0[nt * 8 + 1] = vv1;
                    vrow1[nt * 8] = vv2; vrow1[nt * 8 + 1] = vv3;
                    if (sizeof(TOUT) == 2) {
                        *(uint32_t*)((__half*)Oz + (size_t)r0 * N_ + cc) =
                            packh(__float2half_rn(s0), __float2half_rn(s1));
                        *(uint32_t*)((__half*)Oz + (size_t)r1 * N_ + cc) =
                            packh(__float2half_rn(s2), __float2half_rn(s3));
                    } else {
                        *(float2*)((float*)Oz + (size_t)r0 * N_ + cc) = make_float2(s0, s1);
                        *(float2*)((float*)Oz + (size_t)r1 * N_ + cc) = make_float2(s2, s3);
                    }
                }
            }
        }
        // no extra sync needed: V cells are thread-private; panel buffers
        // are protected by the K-loop's own __syncthreads.
    }
}

// ============================================================================
// kv[t,b,h,d1,d2] = sum_n Sk[.,d1,n]*Sv[.,d2,n]   (binary fp16 in, exact)
// ============================================================================
__global__ __launch_bounds__(256) void kv_kernel()
{
    int tbh = blockIdx.x;
    int tb = tbh >> 3, h = tbh & 7;
    const __half* K = gh_k + (size_t)tb * CN + (size_t)h * 64 * N_;
    const __half* V = gh_v + (size_t)tb * CN + (size_t)h * 64 * N_;

    __shared__ float Ks[64][65];
    __shared__ float Vs[64][65];

    const int tid = threadIdx.x;
    const int tx = tid & 15, ty = tid >> 4;
    const int r = tid >> 2;
    const int c0 = (tid & 3) * 4;

    float acc[4][4];
#pragma unroll
    for (int i = 0; i < 4; i++)
#pragma unroll
        for (int j = 0; j < 4; j++) acc[i][j] = 0.0f;

    for (int nc = 0; nc < 16; nc++) {
        int nbase = nc * 64;
        __syncthreads();
#pragma unroll
        for (int c4 = 0; c4 < 4; c4++) {
            int nn = c0 + c4 * 16;
            uint2 ku = *(const uint2*)(K + (size_t)r * N_ + nbase + nn);
            uint2 vu = *(const uint2*)(V + (size_t)r * N_ + nbase + nn);
            float2 k0 = __half22float2(*(__half2*)&ku.x);
            float2 k1 = __half22float2(*(__half2*)&ku.y);
            float2 v0 = __half22float2(*(__half2*)&vu.x);
            float2 v1 = __half22float2(*(__half2*)&vu.y);
            Ks[nn + 0][r] = k0.x; Ks[nn + 1][r] = k0.y;
            Ks[nn + 2][r] = k1.x; Ks[nn + 3][r] = k1.y;
            Vs[nn + 0][r] = v0.x; Vs[nn + 1][r] = v0.y;
            Vs[nn + 2][r] = v1.x; Vs[nn + 3][r] = v1.y;
        }
        __syncthreads();
#pragma unroll 8
        for (int nn = 0; nn < 64; nn++) {
            float a_[4], b_[4];
#pragma unroll
            for (int i = 0; i < 4; i++) a_[i] = Ks[nn][ty * 4 + i];
#pragma unroll
            for (int j = 0; j < 4; j++) b_[j] = Vs[nn][tx * 4 + j];
#pragma unroll
            for (int i = 0; i < 4; i++)
#pragma unroll
                for (int j = 0; j < 4; j++)
                    acc[i][j] += a_[i] * b_[j];
        }
    }

    float* kvb = g_kv + (size_t)tbh * 4096;
#pragma unroll
    for (int i = 0; i < 4; i++)
#pragma unroll
        for (int j = 0; j < 4; j++)
            kvb[(ty * 4 + i) * 64 + (tx * 4 + j)] = acc[i][j];
}

// ============================================================================
// av + fused attn-LIF: block (n-tile, b*8+h), loops t with v-state in regs.
// a[e,n] = 0.125 * sum_d Sq[d,n]*kv[d,e]  -> LIF(0.5) -> fp16 spikes gh_a.
// ============================================================================
__global__ __launch_bounds__(256) void av_lif()
{
    const int bh = blockIdx.y;          // 0..63
    const int b = bh >> 3, h = bh & 7;
    const int n0 = blockIdx.x * 128;

    __shared__ float Qs[64][128];
    __shared__ float KVs[64][64];

    const int tid = threadIdx.x;
    const int tx = tid & 31, ty = tid >> 5;

    float v[8][4];
#pragma unroll
    for (int i = 0; i < 8; i++)
#pragma unroll
        for (int j = 0; j < 4; j++) v[i][j] = 0.0f;

#pragma unroll 1
    for (int t = 0; t < 4; t++) {
        const int tb = t * 8 + b;
        const __half* Q  = gh_q + (size_t)tb * CN + (size_t)h * 64 * N_;
        const float*  KV = g_kv + ((size_t)tb * 8 + h) * 4096;

        __syncthreads();
#pragma unroll
        for (int i = 0; i < 4; i++) {
            int idx = tid + i * 256;
            int r = idx >> 4, c = (idx & 15) * 4;
            *(float4*)&KVs[r][c] = *(const float4*)(KV + (size_t)r * 64 + c);
        }
#pragma unroll
        for (int i = 0; i < 8; i++) {
            int idx = tid + i * 256;
            int r = idx >> 5, c = (idx & 31) * 4;
            uint2 qu = *(const uint2*)(Q + (size_t)r * N_ + n0 + c);
            float2 q0 = __half22float2(*(__half2*)&qu.x);
            float2 q1 = __half22float2(*(__half2*)&qu.y);
            Qs[r][c] = q0.x; Qs[r][c + 1] = q0.y;
            Qs[r][c + 2] = q1.x; Qs[r][c + 3] = q1.y;
        }
        __syncthreads();

        float acc[8][4];
#pragma unroll
        for (int i = 0; i < 8; i++)
#pragma unroll
            for (int j = 0; j < 4; j++) acc[i][j] = 0.0f;

#pragma unroll 8
        for (int d = 0; d < 64; d++) {
            float4 q4 = *(const float4*)&Qs[d][tx * 4];
#pragma unroll
            for (int i = 0; i < 8; i++) {
                float kvv = KVs[d][ty * 8 + i];
                acc[i][0] += kvv * q4.x;
                acc[i][1] += kvv * q4.y;
                acc[i][2] += kvv * q4.z;
                acc[i][3] += kvv * q4.w;
            }
        }

        __half* A = gh_a + (size_t)tb * CN + (size_t)h * 64 * N_;
#pragma unroll
        for (int i = 0; i < 8; i++) {
            int e = ty * 8 + i;
            __half sp[4];
#pragma unroll
            for (int j = 0; j < 4; j++) {
                float x = __fmul_rn(acc[i][j], 0.125f);
                float s = lif_step(v[i][j], x, 0.5f);
                sp[j] = __float2half_rn(s);
            }
            *(uint2*)(A + (size_t)e * N_ + n0 + tx * 4) =
                make_uint2(packh(sp[0], sp[1]), packh(sp[2], sp[3]));
        }
    }
}

// ============================================================================
extern "C" void kernel_launch(void* const* d_in, const int* in_sizes, int n_in,
                              void* d_out, int out_size)
{
    const float* x   = (const float*)d_in[0];
    const float* Wq  = (const float*)d_in[1];
    const float* qg  = (const float*)d_in[2];
    const float* qb  = (const float*)d_in[3];
    const float* Wk  = (const float*)d_in[4];
    const float* kg  = (const float*)d_in[5];
    const float* kb  = (const float*)d_in[6];
    const float* Wv  = (const float*)d_in[7];
    const float* vg  = (const float*)d_in[8];
    const float* vb  = (const float*)d_in[9];
    const float* Wp  = (const float*)d_in[10];
    const float* bp  = (const float*)d_in[11];
    const float* pg  = (const float*)d_in[12];
    const float* pb  = (const float*)d_in[13];
    float* out = (float*)d_out;

    __half *hq, *hk, *hv, *ha;
    cudaGetSymbolAddress((void**)&hq, gh_q);
    cudaGetSymbolAddress((void**)&hk, gh_k);
    cudaGetSymbolAddress((void**)&hv, gh_v);
    cudaGetSymbolAddress((void**)&ha, gh_a);

    float one_eps = 1.0f + 1e-5f;
    float inv = (float)(1.0 / sqrt((double)one_eps));

    const int SMEM = 32768 + 128 * 130 * 4;   // 99328
    cudaFuncSetAttribute((const void*)gemm_lif<3, __half>,
                         cudaFuncAttributeMaxDynamicSharedMemorySize, SMEM);
    cudaFuncSetAttribute((const void*)gemm_lif<2, float>,
                         cudaFuncAttributeMaxDynamicSharedMemorySize, SMEM);

    dim3 gg(N_ / 128, C_ / 128, B_);   // 8 x 4 x 8

    gemm_lif<3, __half><<<gg, 256, SMEM>>>(Wq, x, hq, qg, qb, nullptr, inv, 1.0f);
    gemm_lif<3, __half><<<gg, 256, SMEM>>>(Wk, x, hk, kg, kb, nullptr, inv, 1.0f);
    gemm_lif<3, __half><<<gg, 256, SMEM>>>(Wv, x, hv, vg, vb, nullptr, inv, 1.0f);

    kv_kernel<<<256, 256>>>();
    av_lif<<<dim3(N_ / 128, 64), 256>>>();

    gemm_lif<2, float><<<gg, 256, SMEM>>>(Wp, ha, out, pg, pb, bp, inv, 1.0f);
}

// round 7
// speedup vs baseline: 1.1448x; 1.1448x over previous
#include <cuda_runtime.h>
#include <cuda_fp16.h>
#include <cmath>
#include <cstdint>

#define T_ 4
#define B_ 8
#define C_ 512
#define N_ 1024
#define TB 32
#define CN (C_*N_)          // 524288
#define TBCN (TB*CN)        // 16777216

// Scratch (static device globals — no runtime allocation)
__device__ __half gh_q[TBCN];        // q spikes [t][b][c][n] fp16 (binary, exact)
__device__ __half gh_k[TBCN];
__device__ __half gh_v[TBCN];
__device__ __half gh_a[TBCN];        // attn spikes
__device__ __half g_kvh[TB*8*64*64]; // kv^T [tbh][e][d], counts <=1024, fp16-exact

#define WSCALE     2048.0f
#define WSCALE_INV 4.8828125e-4f     // 2^-11, exact

// ============================================================================
// helpers
// ============================================================================
__device__ __forceinline__ uint32_t smem_u32(const void* p) {
    uint32_t a;
    asm("{ .reg .u64 t; cvta.to.shared.u64 t, %1; cvt.u32.u64 %0, t; }" : "=r"(a) : "l"(p));
    return a;
}
__device__ __forceinline__ uint32_t packh(__half a, __half b) {
    __half2 h = __halves2half2(a, b);
    return *(uint32_t*)&h;
}
__device__ __forceinline__ void ldmx4(uint32_t* r, uint32_t addr) {
    asm volatile("ldmatrix.sync.aligned.m8n8.x4.shared.b16 {%0,%1,%2,%3}, [%4];"
                 : "=r"(r[0]), "=r"(r[1]), "=r"(r[2]), "=r"(r[3]) : "r"(addr));
}
__device__ __forceinline__ void ldmx4t(uint32_t* r, uint32_t addr) {
    asm volatile("ldmatrix.sync.aligned.m8n8.x4.trans.shared.b16 {%0,%1,%2,%3}, [%4];"
                 : "=r"(r[0]), "=r"(r[1]), "=r"(r[2]), "=r"(r[3]) : "r"(addr));
}
__device__ __forceinline__ void mma16(float* c, const uint32_t* a, const uint32_t* b) {
    asm volatile("mma.sync.aligned.m16n8k16.row.col.f32.f16.f16.f32 "
                 "{%0,%1,%2,%3}, {%4,%5,%6,%7}, {%8,%9}, {%0,%1,%2,%3};"
                 : "+f"(c[0]), "+f"(c[1]), "+f"(c[2]), "+f"(c[3])
                 : "r"(a[0]), "r"(a[1]), "r"(a[2]), "r"(a[3]), "r"(b[0]), "r"(b[1]));
}
// exact reference LIF step: v' = v + (x - v)*0.5 ; spike >= thr ; hard reset
__device__ __forceinline__ float lif_step(float& vv, float x, float thr) {
    vv = __fadd_rn(vv, __fmul_rn(__fsub_rn(x, vv), 0.5f));
    float s = (vv >= thr) ? 1.0f : 0.0f;
    if (vv >= thr) vv = 0.0f;
    return s;
}

// ============================================================================
// Fused fp16-split GEMM + BN + multi-step LIF (unchanged from R6, proven).
// ============================================================================
template<int NSPLIT, typename TOUT>
__global__ __launch_bounds__(256, 2) void gemm_lif(
    const float* __restrict__ W, const void* __restrict__ Xv,
    TOUT* __restrict__ OUT,
    const float* __restrict__ gamma, const float* __restrict__ beta,
    const float* __restrict__ bias, float inv, float thr)
{
    extern __shared__ char smbuf[];
    const uint32_t sbase = smem_u32(smbuf);
    float* Vst = (float*)(smbuf + 32768);

    const int tid  = threadIdx.x;
    const int lane = tid & 31;
    const int wid  = tid >> 5;
    const int wm   = (wid >> 2) * 64;
    const int wn   = (wid & 3) * 32;
    const int b  = blockIdx.z;
    const int m0 = blockIdx.y * 128;
    const int n0 = blockIdx.x * 128;

#pragma unroll
    for (int i = tid; i < 128 * 130 / 2; i += 256)
        *(float2*)&Vst[i * 2] = make_float2(0.0f, 0.0f);

    const int mA = tid & 127;
    const int jA = (tid >> 7) * 8;
    const int kB = tid >> 5;
    const int nB = (tid & 31) * 4;
    const float* Wrow = W + (size_t)(m0 + mA) * C_ + jA;
    const uint32_t abyte = (uint32_t)((mA * 2 + ((jA >> 3) ^ ((mA >> 2) & 1))) * 16);
    const uint32_t bbyte0 = (uint32_t)(kB * 256 + (((nB >> 3) ^ (kB & 7))) * 16 + (nB & 7) * 2);
    const int kB2 = kB + 8;
    const uint32_t bbyte1 = (uint32_t)(kB2 * 256 + (((nB >> 3) ^ (kB2 & 7))) * 16 + (nB & 7) * 2);

    const int mrel = (lane & 7) | (((lane >> 3) & 1) << 3);
    const int hA   = (lane >> 4) & 1;
    uint32_t offA[4];
#pragma unroll
    for (int mt = 0; mt < 4; mt++) {
        int m = wm + mt * 16 + mrel;
        offA[mt] = (uint32_t)((m * 2 + (hA ^ ((m >> 2) & 1))) * 16);
    }
    const int krel = (lane & 7) | (((lane >> 3) & 1) << 3);
    const int nrel = ((lane >> 4) & 1) * 8;
    uint32_t offB[2];
#pragma unroll
    for (int p = 0; p < 2; p++) {
        int n = wn + p * 16 + nrel;
        offB[p] = (uint32_t)(krel * 256 + (((n >> 3) ^ (krel & 7))) * 16);
    }

    __syncthreads();

#pragma unroll 1
    for (int t = 0; t < 4; t++) {
        const size_t zoff = (size_t)(t * 8 + b) * CN;
        const float*  Xf = (const float*)Xv + zoff;
        const __half* Xh = (const __half*)Xv + zoff;

        float acc[4][4][4];
#pragma unroll
        for (int i = 0; i < 4; i++)
#pragma unroll
            for (int j = 0; j < 4; j++)
#pragma unroll
                for (int e = 0; e < 4; e++) acc[i][j][e] = 0.0f;

        float4 wa0, wa1, xb0, xb1;
        uint2 ub0, ub1;

        auto LDG = [&](int ch) {
            const int kb = ch * 16;
            wa0 = *(const float4*)(Wrow + kb);
            wa1 = *(const float4*)(Wrow + kb + 4);
            if (NSPLIT >= 3) {
                xb0 = *(const float4*)(Xf + (size_t)(kb + kB) * N_ + n0 + nB);
                xb1 = *(const float4*)(Xf + (size_t)(kb + 8 + kB) * N_ + n0 + nB);
            } else {
                ub0 = *(const uint2*)(Xh + (size_t)(kb + kB) * N_ + n0 + nB);
                ub1 = *(const uint2*)(Xh + (size_t)(kb + 8 + kB) * N_ + n0 + nB);
            }
        };

        auto STS = [&](int st) {
            char* Ah = smbuf + st * 4096;
            char* Al = smbuf + 8192 + st * 4096;
            char* Bh = smbuf + 16384 + st * 4096;
            char* Bl = smbuf + 24576 + st * 4096;
            float wv[8] = {wa0.x, wa0.y, wa0.z, wa0.w, wa1.x, wa1.y, wa1.z, wa1.w};
            uint32_t ph[4], pl[4];
#pragma unroll
            for (int e = 0; e < 4; e++) {
                float s0 = wv[2 * e] * WSCALE, s1 = wv[2 * e + 1] * WSCALE;
                __half h0 = __float2half_rn(s0), h1 = __float2half_rn(s1);
                __half l0 = __float2half_rn(s0 - __half2float(h0));
                __half l1 = __float2half_rn(s1 - __half2float(h1));
                ph[e] = packh(h0, h1);
                pl[e] = packh(l0, l1);
            }
            *(uint4*)(Ah + abyte) = make_uint4(ph[0], ph[1], ph[2], ph[3]);
            *(uint4*)(Al + abyte) = make_uint4(pl[0], pl[1], pl[2], pl[3]);
            if (NSPLIT >= 3) {
                __half h0 = __float2half_rn(xb0.x), h1 = __float2half_rn(xb0.y);
                __half h2 = __float2half_rn(xb0.z), h3 = __float2half_rn(xb0.w);
                __half l0 = __float2half_rn(xb0.x - __half2float(h0));
                __half l1 = __float2half_rn(xb0.y - __half2float(h1));
                __half l2 = __float2half_rn(xb0.z - __half2float(h2));
                __half l3 = __float2half_rn(xb0.w - __half2float(h3));
                *(uint2*)(Bh + bbyte0) = make_uint2(packh(h0, h1), packh(h2, h3));
                *(uint2*)(Bl + bbyte0) = make_uint2(packh(l0, l1), packh(l2, l3));
                h0 = __float2half_rn(xb1.x); h1 = __float2half_rn(xb1.y);
                h2 = __float2half_rn(xb1.z); h3 = __float2half_rn(xb1.w);
                l0 = __float2half_rn(xb1.x - __half2float(h0));
                l1 = __float2half_rn(xb1.y - __half2float(h1));
                l2 = __float2half_rn(xb1.z - __half2float(h2));
                l3 = __float2half_rn(xb1.w - __half2float(h3));
                *(uint2*)(Bh + bbyte1) = make_uint2(packh(h0, h1), packh(h2, h3));
                *(uint2*)(Bl + bbyte1) = make_uint2(packh(l0, l1), packh(l2, l3));
            } else {
                *(uint2*)(Bh + bbyte0) = ub0;
                *(uint2*)(Bh + bbyte1) = ub1;
            }
        };

        auto COMP = [&](int st) {
            const uint32_t aHi = sbase + st * 4096;
            const uint32_t aLo = sbase + 8192 + st * 4096;
            const uint32_t bHi = sbase + 16384 + st * 4096;
            const uint32_t bLo = sbase + 24576 + st * 4096;

            uint32_t ah[4][4], bh[4][2];
#pragma unroll
            for (int mt = 0; mt < 4; mt++) ldmx4(ah[mt], aHi + offA[mt]);
#pragma unroll
            for (int p = 0; p < 2; p++) {
                uint32_t tr[4];
                ldmx4t(tr, bHi + offB[p]);
                bh[2 * p][0] = tr[0]; bh[2 * p][1] = tr[1];
                bh[2 * p + 1][0] = tr[2]; bh[2 * p + 1][1] = tr[3];
            }
#pragma unroll
            for (int mt = 0; mt < 4; mt++)
#pragma unroll
                for (int nt = 0; nt < 4; nt++) mma16(acc[mt][nt], ah[mt], bh[nt]);
            if (NSPLIT >= 3) {
                uint32_t bl[4][2];
#pragma unroll
                for (int p = 0; p < 2; p++) {
                    uint32_t tr[4];
                    ldmx4t(tr, bLo + offB[p]);
                    bl[2 * p][0] = tr[0]; bl[2 * p][1] = tr[1];
                    bl[2 * p + 1][0] = tr[2]; bl[2 * p + 1][1] = tr[3];
                }
#pragma unroll
                for (int mt = 0; mt < 4; mt++)
#pragma unroll
                    for (int nt = 0; nt < 4; nt++) mma16(acc[mt][nt], ah[mt], bl[nt]);
            }
#pragma unroll
            for (int mt = 0; mt < 4; mt++) ldmx4(ah[mt], aLo + offA[mt]);
#pragma unroll
            for (int mt = 0; mt < 4; mt++)
#pragma unroll
                for (int nt = 0; nt < 4; nt++) mma16(acc[mt][nt], ah[mt], bh[nt]);
        };

        LDG(0);
        STS(0);
        __syncthreads();
#pragma unroll 1
        for (int ch = 0; ch < 32; ch++) {
            if (ch < 31) LDG(ch + 1);
            COMP(ch & 1);
            if (ch < 31) STS((ch + 1) & 1);
            __syncthreads();
        }

        {
            const int rb = m0 + wm + (lane >> 2);
            const int cb = n0 + wn + 2 * (lane & 3);
            const int rlb = wm + (lane >> 2);
            const int clb = wn + 2 * (lane & 3);
            TOUT* Oz = OUT + zoff;
#pragma unroll
            for (int mt = 0; mt < 4; mt++) {
                int r0 = rb + mt * 16, r1 = r0 + 8;
                float g0 = gamma[r0], g1 = gamma[r1];
                float e0 = beta[r0],  e1 = beta[r1];
                float b0 = bias ? bias[r0] : 0.0f;
                float b1 = bias ? bias[r1] : 0.0f;
                float* vrow0 = &Vst[(rlb + mt * 16) * 130 + clb];
                float* vrow1 = vrow0 + 8 * 130;
#pragma unroll
                for (int nt = 0; nt < 4; nt++) {
                    int cc = cb + nt * 8;
                    float* c = acc[mt][nt];
                    float y0 = __fmul_rn(c[0], WSCALE_INV);
                    float y1 = __fmul_rn(c[1], WSCALE_INV);
                    float y2 = __fmul_rn(c[2], WSCALE_INV);
                    float y3 = __fmul_rn(c[3], WSCALE_INV);
                    if (bias) { y0 = __fadd_rn(y0, b0); y1 = __fadd_rn(y1, b0);
                                y2 = __fadd_rn(y2, b1); y3 = __fadd_rn(y3, b1); }
                    y0 = __fadd_rn(__fmul_rn(__fmul_rn(g0, y0), inv), e0);
                    y1 = __fadd_rn(__fmul_rn(__fmul_rn(g0, y1), inv), e0);
                    y2 = __fadd_rn(__fmul_rn(__fmul_rn(g1, y2), inv), e1);
                    y3 = __fadd_rn(__fmul_rn(__fmul_rn(g1, y3), inv), e1);
                    float vv0 = vrow0[nt * 8],     vv1 = vrow0[nt * 8 + 1];
                    float vv2 = vrow1[nt * 8],     vv3 = vrow1[nt * 8 + 1];
                    float s0 = lif_step(vv0, y0, thr);
                    float s1 = lif_step(vv1, y1, thr);
                    float s2 = lif_step(vv2, y2, thr);
                    float s3 = lif_step(vv3, y3, thr);
                    vrow0[nt * 8] = vv0; vrow0[nt * 8 + 1] = vv1;
                    vrow1[nt * 8] = vv2; vrow1[nt * 8 + 1] = vv3;
                    if (sizeof(TOUT) == 2) {
                        *(uint32_t*)((__half*)Oz + (size_t)r0 * N_ + cc) =
                            packh(__float2half_rn(s0), __float2half_rn(s1));
                        *(uint32_t*)((__half*)Oz + (size_t)r1 * N_ + cc) =
                            packh(__float2half_rn(s2), __float2half_rn(s3));
                    } else {
                        *(float2*)((float*)Oz + (size_t)r0 * N_ + cc) = make_float2(s0, s1);
                        *(float2*)((float*)Oz + (size_t)r1 * N_ + cc) = make_float2(s2, s3);
                    }
                }
            }
        }
    }
}

// ============================================================================
// kv via tensor cores: kv[d][e] = sum_n' K[d][n'] V[e][n']   (binary, exact)
// A = K rows (m=d), plain ldmatrix.  B = V rows ([e][n'] = col-major k x n,
// plain ldmatrix gives the B fragment).  Output stored TRANSPOSED as fp16:
// g_kvh[tbh][e][d]  (counts <= 1024, exact in fp16).
// Block per tbh; 8 warps: warp w -> m-tile (w&3)*16, n-half (w>>2)*32.
// 8 chunks of kc=128 spatial, single-buffered smem.
// ============================================================================
__global__ __launch_bounds__(256) void kv_mma()
{
    __shared__ char sK[16384];   // [64 rows][128 halves] swizzled
    __shared__ char sV[16384];

    const int tbh = blockIdx.x;
    const int tb = tbh >> 3, h = tbh & 7;
    const __half* K = gh_k + (size_t)tb * CN + (size_t)h * 64 * N_;
    const __half* V = gh_v + (size_t)tb * CN + (size_t)h * 64 * N_;

    const int tid = threadIdx.x;
    const int lane = tid & 31;
    const int w = tid >> 5;
    const int mt = (w & 3) * 16;       // m base (d)
    const int nh = (w >> 2) * 32;      // n base (e)

    const uint32_t skb = smem_u32(sK);
    const uint32_t svb = smem_u32(sV);

    float acc[4][4];
#pragma unroll
    for (int i = 0; i < 4; i++)
#pragma unroll
        for (int j = 0; j < 4; j++) acc[i][j] = 0.0f;

    // loader: 128 threads per matrix, 8 uint4 each
    const __half* src = (tid < 128) ? K : V;
    char* dstp = (tid < 128) ? sK : sV;
    const int lt = tid & 127;

#pragma unroll 1
    for (int c = 0; c < 8; c++) {
        __syncthreads();
#pragma unroll
        for (int i = 0; i < 8; i++) {
            int idx = lt + i * 128;            // 0..1023
            int row = idx >> 4, seg = idx & 15;
            int phys = seg ^ (row & 7);
            *(uint4*)(dstp + row * 256 + phys * 16) =
                *(const uint4*)(src + (size_t)row * N_ + c * 128 + seg * 8);
        }
        __syncthreads();

#pragma unroll
        for (int j = 0; j < 8; j++) {          // k16 steps within chunk
            uint32_t a[4];
            {
                int row = mt + (lane & 7) + ((lane >> 3) & 1) * 8;
                int seg = 2 * j + (lane >> 4);
                ldmx4(a, skb + row * 256 + (seg ^ (row & 7)) * 16);
            }
#pragma unroll
            for (int p = 0; p < 2; p++) {
                uint32_t r[4];
                int row = nh + p * 16 + (lane & 7) + ((lane >> 4) & 1) * 8;
                int seg = 2 * j + ((lane >> 3) & 1);
                ldmx4(r, svb + row * 256 + (seg ^ (row & 7)) * 16);
                mma16(acc[2 * p],     a, &r[0]);
                mma16(acc[2 * p + 1], a, &r[2]);
            }
        }
    }

    // store transposed fp16: g_kvh[tbh][e][d]
    __half* out = g_kvh + (size_t)tbh * 4096;
    const int d0 = mt + (lane >> 2);
    const int eb = nh + 2 * (lane & 3);
#pragma unroll
    for (int nt = 0; nt < 4; nt++) {
        int e = eb + nt * 8;
        out[(size_t)e * 64 + d0]           = __float2half_rn(acc[nt][0]);
        out[(size_t)(e + 1) * 64 + d0]     = __float2half_rn(acc[nt][1]);
        out[(size_t)e * 64 + d0 + 8]       = __float2half_rn(acc[nt][2]);
        out[(size_t)(e + 1) * 64 + d0 + 8] = __float2half_rn(acc[nt][3]);
    }
}

// ============================================================================
// av via tensor cores + fused attn-LIF.
// a[e][n] = 0.125 * sum_d q[d][n] * kvT[e][d]; LIF(0.5) over t in registers.
// A = kvT [e][d] (plain ldmx4).  B = q [d][n] ([k][n] panel + ldmx4t, the
// proven gemm-B pattern).  Block = (n-chunk 128, b*8+h); warp w -> n strip 16.
// ============================================================================
__global__ __launch_bounds__(256, 2) void av_lif_mma()
{
    __shared__ char sA[8192];    // kvT [64 e][64 d] swizzled (128B rows)
    __shared__ char sQ[32768];   // q [64 d][128 n] swizzled (256B rows)

    const int bh = blockIdx.y;
    const int b = bh >> 3, h = bh & 7;
    const int n0 = blockIdx.x * 128;

    const int tid = threadIdx.x;
    const int lane = tid & 31;
    const int w = tid >> 5;

    const uint32_t sab = smem_u32(sA);
    const uint32_t sqb = smem_u32(sQ);

    // ldmatrix offsets
    const int mrel = (lane & 7) + ((lane >> 3) & 1) * 8;
    const int hA = (lane >> 4) & 1;
    const int krel = (lane & 7) | (((lane >> 3) & 1) << 3);
    const int nrel = ((lane >> 4) & 1) * 8;
    const int nseg = (w * 16 + nrel) >> 3;   // n-seg index (0..15)

    float vst[4][2][4];
#pragma unroll
    for (int i = 0; i < 4; i++)
#pragma unroll
        for (int j = 0; j < 2; j++)
#pragma unroll
            for (int e = 0; e < 4; e++) vst[i][j][e] = 0.0f;

#pragma unroll 1
    for (int t = 0; t < 4; t++) {
        const int tb = t * 8 + b;
        const __half* KV = g_kvh + ((size_t)tb * 8 + h) * 4096;
        const __half* Q  = gh_q + (size_t)tb * CN + (size_t)h * 64 * N_;

        __syncthreads();
        // load kvT: 512 uint4, 2 per thread
#pragma unroll
        for (int i = 0; i < 2; i++) {
            int idx = tid + i * 256;
            int e = idx >> 3, seg = idx & 7;
            int phys = seg ^ (e & 7);
            *(uint4*)(sA + e * 128 + phys * 16) =
                *(const uint4*)(KV + (size_t)e * 64 + seg * 8);
        }
        // load q chunk: 1024 uint4, 4 per thread
#pragma unroll
        for (int i = 0; i < 4; i++) {
            int idx = tid + i * 256;
            int d = idx >> 4, seg = idx & 15;
            int phys = seg ^ (d & 7);
            *(uint4*)(sQ + d * 256 + phys * 16) =
                *(const uint4*)(Q + (size_t)d * N_ + n0 + seg * 8);
        }
        __syncthreads();

        float acc[4][2][4];
#pragma unroll
        for (int i = 0; i < 4; i++)
#pragma unroll
            for (int j = 0; j < 2; j++)
#pragma unroll
                for (int e = 0; e < 4; e++) acc[i][j][e] = 0.0f;

#pragma unroll
        for (int j = 0; j < 4; j++) {          // k16 steps (d)
            uint32_t bq[2][2];
            {
                uint32_t tr[4];
                int kr = j * 16 + krel;
                ldmx4t(tr, sqb + kr * 256 + ((nseg ^ (kr & 7))) * 16);
                bq[0][0] = tr[0]; bq[0][1] = tr[1];
                bq[1][0] = tr[2]; bq[1][1] = tr[3];
            }
#pragma unroll
            for (int mt = 0; mt < 4; mt++) {
                uint32_t a[4];
                int row = mt * 16 + mrel;
                int seg = 2 * j + hA;
                ldmx4(a, sab + row * 128 + ((seg ^ (row & 7))) * 16);
                mma16(acc[mt][0], a, bq[0]);
                mma16(acc[mt][1], a, bq[1]);
            }
        }

        // epilogue: *0.125 (exact), LIF, write fp16 spikes
        __half* A = gh_a + (size_t)tb * CN + (size_t)h * 64 * N_;
        const int cb = n0 + w * 16 + 2 * (lane & 3);
#pragma unroll
        for (int mt = 0; mt < 4; mt++) {
            int e0 = mt * 16 + (lane >> 2), e1 = e0 + 8;
#pragma unroll
            for (int nt = 0; nt < 2; nt++) {
                int cc = cb + nt * 8;
                float* c = acc[mt][nt];
                float* vv = vst[mt][nt];
                float s0 = lif_step(vv[0], __fmul_rn(c[0], 0.125f), 0.5f);
                float s1 = lif_step(vv[1], __fmul_rn(c[1], 0.125f), 0.5f);
                float s2 = lif_step(vv[2], __fmul_rn(c[2], 0.125f), 0.5f);
                float s3 = lif_step(vv[3], __fmul_rn(c[3], 0.125f), 0.5f);
                *(uint32_t*)(A + (size_t)e0 * N_ + cc) =
                    packh(__float2half_rn(s0), __float2half_rn(s1));
                *(uint32_t*)(A + (size_t)e1 * N_ + cc) =
                    packh(__float2half_rn(s2), __float2half_rn(s3));
            }
        }
    }
}

// ============================================================================
extern "C" void kernel_launch(void* const* d_in, const int* in_sizes, int n_in,
                              void* d_out, int out_size)
{
    const float* x   = (const float*)d_in[0];
    const float* Wq  = (const float*)d_in[1];
    const float* qg  = (const float*)d_in[2];
    const float* qb  = (const float*)d_in[3];
    const float* Wk  = (const float*)d_in[4];
    const float* kg  = (const float*)d_in[5];
    const float* kb  = (const float*)d_in[6];
    const float* Wv  = (const float*)d_in[7];
    const float* vg  = (const float*)d_in[8];
    const float* vb  = (const float*)d_in[9];
    const float* Wp  = (const float*)d_in[10];
    const float* bp  = (const float*)d_in[11];
    const float* pg  = (const float*)d_in[12];
    const float* pb  = (const float*)d_in[13];
    float* out = (float*)d_out;

    __half *hq, *hk, *hv, *ha;
    cudaGetSymbolAddress((void**)&hq, gh_q);
    cudaGetSymbolAddress((void**)&hk, gh_k);
    cudaGetSymbolAddress((void**)&hv, gh_v);
    cudaGetSymbolAddress((void**)&ha, gh_a);

    float one_eps = 1.0f + 1e-5f;
    float inv = (float)(1.0 / sqrt((double)one_eps));

    const int SMEM = 32768 + 128 * 130 * 4;   // 99328
    cudaFuncSetAttribute((const void*)gemm_lif<3, __half>,
                         cudaFuncAttributeMaxDynamicSharedMemorySize, SMEM);
    cudaFuncSetAttribute((const void*)gemm_lif<2, float>,
                         cudaFuncAttributeMaxDynamicSharedMemorySize, SMEM);

    dim3 gg(N_ / 128, C_ / 128, B_);   // 8 x 4 x 8

    gemm_lif<3, __half><<<gg, 256, SMEM>>>(Wq, x, hq, qg, qb, nullptr, inv, 1.0f);
    gemm_lif<3, __half><<<gg, 256, SMEM>>>(Wk, x, hk, kg, kb, nullptr, inv, 1.0f);
    gemm_lif<3, __half><<<gg, 256, SMEM>>>(Wv, x, hv, vg, vb, nullptr, inv, 1.0f);

    kv_mma<<<256, 256>>>();
    av_lif_mma<<<dim3(8, 64), 256>>>();

    gemm_lif<2, float><<<gg, 256, SMEM>>>(Wp, ha, out, pg, pb, bp, inv, 1.0f);
}